// round 2
// baseline (speedup 1.0000x reference)
#include <cuda_runtime.h>
#include <math.h>

// Problem constants
#define B_  32
#define T_  2048
#define D_  512
#define H_  512
#define G_  2048          // 4*H
#define BT_ 65536         // B*T
#define NCTA_REC 128

// ---------------------------------------------------------------------------
// Scratch (device globals per harness rules: no cudaMalloc anywhere)
// ---------------------------------------------------------------------------
__device__ float g_xg[65536ULL * 2048ULL];   // (T, B, G) layout: xg[t][b][g]
__device__ float g_h[2][B_ * H_];            // double-buffered hidden state
__device__ unsigned g_flags[NCTA_REC];       // monotone per-CTA barrier flags

// ---------------------------------------------------------------------------
// Acquire/release helpers for the flag barrier
// ---------------------------------------------------------------------------
__device__ __forceinline__ unsigned ld_acq_u32(const unsigned* p) {
    unsigned v;
    asm volatile("ld.acquire.gpu.global.u32 %0, [%1];" : "=r"(v) : "l"(p));
    return v;
}
__device__ __forceinline__ void st_rel_u32(unsigned* p, unsigned v) {
    asm volatile("st.release.gpu.global.u32 [%0], %1;" :: "l"(p), "r"(v));
}

// ---------------------------------------------------------------------------
// Kernel A: xg[t][b][g] = sum_d x[b][t][d] * W[d][g] + bias[g]
// fp32 SIMT GEMM, 128x128 tile, BK=8, 256 threads, 8x8 per-thread tile.
// (unchanged from round 1 — known correct)
// ---------------------------------------------------------------------------
__global__ __launch_bounds__(256) void xg_gemm(const float* __restrict__ x,
                                               const float* __restrict__ W,
                                               const float* __restrict__ bias) {
    __shared__ float As[8][128];   // As[k][m]
    __shared__ float Ws[8][128];   // Ws[k][n]

    const int rowBase = blockIdx.y * 128;   // row in (B*T) space
    const int colBase = blockIdx.x * 128;   // col in G space
    const int tid = threadIdx.x;

    const int arow = tid >> 1;              // 0..127
    const int ak4  = (tid & 1) * 4;         // 0 or 4
    const int wrow = tid >> 5;              // 0..7
    const int wc4  = (tid & 31) * 4;        // 0..124
    const int tm   = (tid >> 4) * 8;        // 0..120
    const int tn   = (tid & 15) * 8;        // 0..120

    float acc[8][8];
#pragma unroll
    for (int i = 0; i < 8; i++)
#pragma unroll
        for (int j = 0; j < 8; j++) acc[i][j] = 0.f;

    for (int k0 = 0; k0 < 512; k0 += 8) {
        float4 av = *(const float4*)&x[(size_t)(rowBase + arow) * 512 + k0 + ak4];
        As[ak4 + 0][arow] = av.x;
        As[ak4 + 1][arow] = av.y;
        As[ak4 + 2][arow] = av.z;
        As[ak4 + 3][arow] = av.w;
        *(float4*)&Ws[wrow][wc4] =
            *(const float4*)&W[(size_t)(k0 + wrow) * 2048 + colBase + wc4];
        __syncthreads();

#pragma unroll
        for (int kk = 0; kk < 8; kk++) {
            float a[8], w[8];
            *(float4*)&a[0] = *(const float4*)&As[kk][tm];
            *(float4*)&a[4] = *(const float4*)&As[kk][tm + 4];
            *(float4*)&w[0] = *(const float4*)&Ws[kk][tn];
            *(float4*)&w[4] = *(const float4*)&Ws[kk][tn + 4];
#pragma unroll
            for (int i = 0; i < 8; i++)
#pragma unroll
                for (int j = 0; j < 8; j++)
                    acc[i][j] = fmaf(a[i], w[j], acc[i][j]);
        }
        __syncthreads();
    }

    float bb[8];
    *(float4*)&bb[0] = *(const float4*)&bias[colBase + tn];
    *(float4*)&bb[4] = *(const float4*)&bias[colBase + tn + 4];

#pragma unroll
    for (int i = 0; i < 8; i++) {
        int r = rowBase + tm + i;
        int t = r & (T_ - 1);
        int b = r >> 11;                       // r / T_
        float* dst = &g_xg[((size_t)t * B_ + b) * G_ + colBase + tn];
        float4 v0 = make_float4(acc[i][0] + bb[0], acc[i][1] + bb[1],
                                acc[i][2] + bb[2], acc[i][3] + bb[3]);
        float4 v1 = make_float4(acc[i][4] + bb[4], acc[i][5] + bb[5],
                                acc[i][6] + bb[6], acc[i][7] + bb[7]);
        *(float4*)&dst[0] = v0;
        *(float4*)&dst[4] = v1;
    }
}

// ---------------------------------------------------------------------------
// Kernel B: persistent recurrence. CTA j owns h-columns [4j, 4j+4) -> 16 gate
// columns {g*512 + 4j + c : g in 0..3, c in 0..3}. Wh slice (two planes for
// vectorized LDS.128) and c-state stay in SMEM across all 2048 steps; only h
// is exchanged via global double buffer + per-CTA flag barrier.
//
// SMEM (floats): Wa[8][516]=4128 | Wb[8][516]=4128 | hs[32*516]=16512
//                | gs[16*32]=512 | cs[128]
// Strides of 516 (== 4 mod 32 words, multiple of 4): LDS.128-aligned and
// bank-conflict-free across the 8 g2 lanes / 4 b lanes of a warp.
// ---------------------------------------------------------------------------
#define WSTRIDE 516
#define SM_WA   0
#define SM_WB   (8 * WSTRIDE)            // 4128
#define SM_HS   (16 * WSTRIDE)           // 8256
#define SM_GS   (SM_HS + 32 * WSTRIDE)   // 8256 + 16512 = 24768
#define SM_CS   (SM_GS + 512)
#define SMEM_FLOATS (SM_CS + 128)

__global__ __launch_bounds__(256) void lstm_rec(const float* __restrict__ W,
                                                const float* __restrict__ h0,
                                                const float* __restrict__ c0,
                                                float* __restrict__ out) {
    extern __shared__ float sm[];
    float* Wa = sm + SM_WA;          // Wa[g2][k], k contiguous
    float* Wb = sm + SM_WB;          // Wb[g2][k]
    float* hs = sm + SM_HS;          // hs[b][k], stride WSTRIDE
    float* gs = sm + SM_GS;          // gs[gl*32 + b]
    float* cs = sm + SM_CS;          // cs[hcl*32 + b]

    const int tid = threadIdx.x;
    const int j   = blockIdx.x;      // 0..127
    const int jb  = j * 4;

    // Load Wh slice into the two planes. gl = gtype*4 + hcl; even gl -> Wa,
    // odd gl -> Wb, plane row = gl>>1 (== g2).
    for (int e = tid; e < 8192; e += 256) {
        int k  = e >> 4;
        int gl = e & 15;
        int gcol = (gl >> 2) * 512 + jb + (gl & 3);
        float v = W[(size_t)(512 + k) * 2048 + gcol];
        float* plane = (gl & 1) ? Wb : Wa;
        plane[(gl >> 1) * WSTRIDE + k] = v;
    }
    // Init c state
    if (tid < 128) {
        int b = tid >> 2, hcl = tid & 3;
        cs[hcl * 32 + b] = c0[b * 512 + jb + hcl];
    }
    // Barrier base: all flags are uniform at run start (monotone across
    // replays: each run adds T_-1 to every flag).
    __shared__ unsigned s_base;
    if (tid == 0) s_base = *(volatile unsigned*)&g_flags[j];
    __syncthreads();
    const unsigned base = s_base;

    const int b     = tid >> 3;            // 0..31
    const int g2    = tid & 7;             // 0..7
    const int gl0   = g2 * 2;              // even gate-local index
    const int gcol0 = (gl0 >> 2) * 512 + jb + (gl0 & 3);

    const float* wa = &Wa[g2 * WSTRIDE];
    const float* wb = &Wb[g2 * WSTRIDE];

    for (int t = 0; t < T_; t++) {
        // Prefetch xg for this thread (independent of h)
        float2 xg2 = *(const float2*)&g_xg[((size_t)t * B_ + b) * G_ + gcol0];

        // Broadcast current h into SMEM
        const float* hsrc = (t == 0) ? h0 : g_h[t & 1];
        for (int i4 = tid; i4 < 4096; i4 += 256) {
            int bb = i4 >> 7, k4 = (i4 & 127) * 4;
            *(float4*)&hs[bb * WSTRIDE + k4] = *(const float4*)&hsrc[bb * 512 + k4];
        }
        __syncthreads();

        // Two K=512 dot products per thread, vectorized: 3x LDS.128 + 8 FFMA
        // per 4 k.
        float acc0 = xg2.x, acc1 = xg2.y;
        const float* hrow = &hs[b * WSTRIDE];
#pragma unroll 4
        for (int k = 0; k < 512; k += 4) {
            float4 h4 = *(const float4*)&hrow[k];
            float4 a4 = *(const float4*)&wa[k];
            float4 b4 = *(const float4*)&wb[k];
            acc0 = fmaf(h4.x, a4.x, acc0); acc1 = fmaf(h4.x, b4.x, acc1);
            acc0 = fmaf(h4.y, a4.y, acc0); acc1 = fmaf(h4.y, b4.y, acc1);
            acc0 = fmaf(h4.z, a4.z, acc0); acc1 = fmaf(h4.z, b4.z, acc1);
            acc0 = fmaf(h4.w, a4.w, acc0); acc1 = fmaf(h4.w, b4.w, acc1);
        }
        gs[gl0 * 32 + b]       = acc0;
        gs[(gl0 + 1) * 32 + b] = acc1;
        __syncthreads();

        // Gate combine: 128 threads, one (b, hcl) each
        if (tid < 128) {
            int bb = tid >> 2, hcl = tid & 3;
            float iv = gs[(0  + hcl) * 32 + bb];
            float fv = gs[(4  + hcl) * 32 + bb];
            float gv = gs[(8  + hcl) * 32 + bb];
            float ov = gs[(12 + hcl) * 32 + bb];
            iv = 1.f / (1.f + expf(-iv));
            fv = 1.f / (1.f + expf(-fv));
            gv = tanhf(gv);
            ov = 1.f / (1.f + expf(-ov));
            float c = fv * cs[hcl * 32 + bb] + iv * gv;
            cs[hcl * 32 + bb] = c;
            float h = ov * tanhf(c);
            g_h[(t + 1) & 1][bb * 512 + jb + hcl] = h;
            out[((size_t)bb * T_ + t) * H_ + jb + hcl] = h;      // outputs[b][t][hc]
            if (t == T_ - 1) {
                out[(size_t)BT_ * H_ + bb * 512 + jb + hcl]            = h;  // h_T
                out[(size_t)BT_ * H_ + B_ * H_ + bb * 512 + jb + hcl]  = c;  // c_T
            }
        }
        __syncthreads();   // orders all g_h stores before tid0's release below

        // Grid barrier via per-CTA monotone flags (skip after last step).
        if (t < T_ - 1) {
            unsigned tgt = base + (unsigned)t + 1u;
            if (tid == 0) st_rel_u32(&g_flags[j], tgt);
            if (tid < NCTA_REC) {
                while ((int)(ld_acq_u32(&g_flags[tid]) - tgt) < 0) { }
            }
            __syncthreads();
        }
    }
}

// ---------------------------------------------------------------------------
// Launcher
// ---------------------------------------------------------------------------
extern "C" void kernel_launch(void* const* d_in, const int* in_sizes, int n_in,
                              void* d_out, int out_size) {
    const float* x    = (const float*)d_in[0];   // (B, T, D)
    const float* W    = (const float*)d_in[1];   // (D+H, 4H)
    const float* bias = (const float*)d_in[2];   // (4H,)
    const float* h0   = (const float*)d_in[3];   // (B, H)
    const float* c0   = (const float*)d_in[4];   // (B, H)
    float* out = (float*)d_out;                  // outputs | h_T | c_T

    dim3 grid(G_ / 128, BT_ / 128);
    xg_gemm<<<grid, 256>>>(x, W, bias);

    size_t smem = SMEM_FLOATS * sizeof(float);
    cudaFuncSetAttribute(lstm_rec, cudaFuncAttributeMaxDynamicSharedMemorySize,
                         (int)smem);
    lstm_rec<<<NCTA_REC, 256, smem>>>(W, h0, c0, out);
}

// round 3
// speedup vs baseline: 1.3773x; 1.3773x over previous
#include <cuda_runtime.h>
#include <math.h>

// Problem constants
#define B_  32
#define T_  2048
#define D_  512
#define H_  512
#define G_  2048          // 4*H
#define BT_ 65536         // B*T
#define NCTA_REC 128

// ---------------------------------------------------------------------------
// Scratch (device globals per harness rules: no cudaMalloc anywhere)
// ---------------------------------------------------------------------------
__device__ float g_xg[65536ULL * 2048ULL];   // (T, B, G) layout: xg[t][b][g]
__device__ float g_h[2][B_ * H_];            // double-buffered hidden state
__device__ unsigned g_flags[NCTA_REC];       // monotone per-CTA arrive flags
__device__ unsigned g_go;                    // monotone master release flag

__device__ __forceinline__ unsigned ld_acq_u32(const unsigned* p) {
    unsigned v;
    asm volatile("ld.acquire.gpu.global.u32 %0, [%1];" : "=r"(v) : "l"(p));
    return v;
}
__device__ __forceinline__ void st_rel_u32(unsigned* p, unsigned v) {
    asm volatile("st.release.gpu.global.u32 [%0], %1;" :: "l"(p), "r"(v));
}

// ---------------------------------------------------------------------------
// Kernel A: xg[t][b][g] = sum_d x[b][t][d] * W[d][g] + bias[g]
// fp32 SIMT GEMM, 128x128 tile, BK=8, 256 threads, 8x8 per-thread tile.
// (unchanged — known correct)
// ---------------------------------------------------------------------------
__global__ __launch_bounds__(256) void xg_gemm(const float* __restrict__ x,
                                               const float* __restrict__ W,
                                               const float* __restrict__ bias) {
    __shared__ float As[8][128];   // As[k][m]
    __shared__ float Ws[8][128];   // Ws[k][n]

    const int rowBase = blockIdx.y * 128;   // row in (B*T) space
    const int colBase = blockIdx.x * 128;   // col in G space
    const int tid = threadIdx.x;

    const int arow = tid >> 1;              // 0..127
    const int ak4  = (tid & 1) * 4;         // 0 or 4
    const int wrow = tid >> 5;              // 0..7
    const int wc4  = (tid & 31) * 4;        // 0..124
    const int tm   = (tid >> 4) * 8;        // 0..120
    const int tn   = (tid & 15) * 8;        // 0..120

    float acc[8][8];
#pragma unroll
    for (int i = 0; i < 8; i++)
#pragma unroll
        for (int j = 0; j < 8; j++) acc[i][j] = 0.f;

    for (int k0 = 0; k0 < 512; k0 += 8) {
        float4 av = *(const float4*)&x[(size_t)(rowBase + arow) * 512 + k0 + ak4];
        As[ak4 + 0][arow] = av.x;
        As[ak4 + 1][arow] = av.y;
        As[ak4 + 2][arow] = av.z;
        As[ak4 + 3][arow] = av.w;
        *(float4*)&Ws[wrow][wc4] =
            *(const float4*)&W[(size_t)(k0 + wrow) * 2048 + colBase + wc4];
        __syncthreads();

#pragma unroll
        for (int kk = 0; kk < 8; kk++) {
            float a[8], w[8];
            *(float4*)&a[0] = *(const float4*)&As[kk][tm];
            *(float4*)&a[4] = *(const float4*)&As[kk][tm + 4];
            *(float4*)&w[0] = *(const float4*)&Ws[kk][tn];
            *(float4*)&w[4] = *(const float4*)&Ws[kk][tn + 4];
#pragma unroll
            for (int i = 0; i < 8; i++)
#pragma unroll
                for (int j = 0; j < 8; j++)
                    acc[i][j] = fmaf(a[i], w[j], acc[i][j]);
        }
        __syncthreads();
    }

    float bb[8];
    *(float4*)&bb[0] = *(const float4*)&bias[colBase + tn];
    *(float4*)&bb[4] = *(const float4*)&bias[colBase + tn + 4];

#pragma unroll
    for (int i = 0; i < 8; i++) {
        int r = rowBase + tm + i;
        int t = r & (T_ - 1);
        int b = r >> 11;                       // r / T_
        float* dst = &g_xg[((size_t)t * B_ + b) * G_ + colBase + tn];
        float4 v0 = make_float4(acc[i][0] + bb[0], acc[i][1] + bb[1],
                                acc[i][2] + bb[2], acc[i][3] + bb[3]);
        float4 v1 = make_float4(acc[i][4] + bb[4], acc[i][5] + bb[5],
                                acc[i][6] + bb[6], acc[i][7] + bb[7]);
        *(float4*)&dst[0] = v0;
        *(float4*)&dst[4] = v1;
    }
}

// ---------------------------------------------------------------------------
// Kernel B: persistent recurrence. CTA j owns h-columns [4j, 4j+4) -> 16 gate
// columns. Wh slice (two planes, LDS.128-friendly) + c-state live in SMEM for
// all 2048 steps; h exchanged via global double buffer + master-aggregated
// barrier:
//   arrive:  each CTA -> st.release g_flags[j] = base + t + 1   (parallel)
//   master:  CTA 0, 128 threads each spin on one flag (coalesced range),
//            then one st.release g_go = go_base + t + 1
//   others:  ONE thread spins on g_go (single shared address), __syncthreads
// Monotone counters => CUDA-graph-replay safe (bases re-read every run; every
// CTA reads its bases before its first arrive, and the master cannot release
// until all CTAs have arrived).
// ---------------------------------------------------------------------------
#define WSTRIDE 516
#define SM_WA   0
#define SM_WB   (8 * WSTRIDE)
#define SM_HS   (16 * WSTRIDE)
#define SM_GS   (SM_HS + 32 * WSTRIDE)
#define SM_CS   (SM_GS + 512)
#define SMEM_FLOATS (SM_CS + 128)

__global__ __launch_bounds__(256) void lstm_rec(const float* __restrict__ W,
                                                const float* __restrict__ h0,
                                                const float* __restrict__ c0,
                                                float* __restrict__ out) {
    extern __shared__ float sm[];
    float* Wa = sm + SM_WA;          // Wa[g2][k]
    float* Wb = sm + SM_WB;          // Wb[g2][k]
    float* hs = sm + SM_HS;          // hs[b][k], stride WSTRIDE
    float* gs = sm + SM_GS;          // gs[gl*32 + b]
    float* cs = sm + SM_CS;          // cs[hcl*32 + b]

    const int tid = threadIdx.x;
    const int j   = blockIdx.x;      // 0..127
    const int jb  = j * 4;

    // Load Wh slice into the two planes.
    for (int e = tid; e < 8192; e += 256) {
        int k  = e >> 4;
        int gl = e & 15;
        int gcol = (gl >> 2) * 512 + jb + (gl & 3);
        float v = W[(size_t)(512 + k) * 2048 + gcol];
        float* plane = (gl & 1) ? Wb : Wa;
        plane[(gl >> 1) * WSTRIDE + k] = v;
    }
    if (tid < 128) {
        int b = tid >> 2, hcl = tid & 3;
        cs[hcl * 32 + b] = c0[b * 512 + jb + hcl];
    }
    // Barrier bases (uniform at run start; monotone across graph replays).
    __shared__ unsigned s_fb, s_gb;
    if (tid == 0) {
        s_fb = *(volatile unsigned*)&g_flags[j];
        s_gb = *(volatile unsigned*)&g_go;
    }
    __syncthreads();
    const unsigned fbase = s_fb;
    const unsigned gbase = s_gb;

    const int b     = tid >> 3;            // 0..31
    const int g2    = tid & 7;             // 0..7
    const int gl0   = g2 * 2;
    const int gcol0 = (gl0 >> 2) * 512 + jb + (gl0 & 3);

    const float* wa = &Wa[g2 * WSTRIDE];
    const float* wb = &Wb[g2 * WSTRIDE];

    for (int t = 0; t < T_; t++) {
        // Prefetch xg for this thread (independent of h)
        float2 xg2 = *(const float2*)&g_xg[((size_t)t * B_ + b) * G_ + gcol0];

        // Broadcast current h into SMEM
        const float* hsrc = (t == 0) ? h0 : g_h[t & 1];
        for (int i4 = tid; i4 < 4096; i4 += 256) {
            int bb = i4 >> 7, k4 = (i4 & 127) * 4;
            *(float4*)&hs[bb * WSTRIDE + k4] = *(const float4*)&hsrc[bb * 512 + k4];
        }
        __syncthreads();

        // Two K=512 dot products per thread: 3x LDS.128 + 8 FFMA per 4 k.
        float acc0 = xg2.x, acc1 = xg2.y;
        const float* hrow = &hs[b * WSTRIDE];
#pragma unroll 4
        for (int k = 0; k < 512; k += 4) {
            float4 h4 = *(const float4*)&hrow[k];
            float4 a4 = *(const float4*)&wa[k];
            float4 b4 = *(const float4*)&wb[k];
            acc0 = fmaf(h4.x, a4.x, acc0); acc1 = fmaf(h4.x, b4.x, acc1);
            acc0 = fmaf(h4.y, a4.y, acc0); acc1 = fmaf(h4.y, b4.y, acc1);
            acc0 = fmaf(h4.z, a4.z, acc0); acc1 = fmaf(h4.z, b4.z, acc1);
            acc0 = fmaf(h4.w, a4.w, acc0); acc1 = fmaf(h4.w, b4.w, acc1);
        }
        gs[gl0 * 32 + b]       = acc0;
        gs[(gl0 + 1) * 32 + b] = acc1;
        __syncthreads();

        // Gate combine: 128 threads, one (b, hcl) each
        if (tid < 128) {
            int bb = tid >> 2, hcl = tid & 3;
            float iv = gs[(0  + hcl) * 32 + bb];
            float fv = gs[(4  + hcl) * 32 + bb];
            float gv = gs[(8  + hcl) * 32 + bb];
            float ov = gs[(12 + hcl) * 32 + bb];
            iv = 1.f / (1.f + expf(-iv));
            fv = 1.f / (1.f + expf(-fv));
            gv = tanhf(gv);
            ov = 1.f / (1.f + expf(-ov));
            float c = fv * cs[hcl * 32 + bb] + iv * gv;
            cs[hcl * 32 + bb] = c;
            float h = ov * tanhf(c);
            g_h[(t + 1) & 1][bb * 512 + jb + hcl] = h;       // critical path
            out[((size_t)bb * T_ + t) * H_ + jb + hcl] = h;  // outputs[b][t][hc]
            if (t == T_ - 1) {
                out[(size_t)BT_ * H_ + bb * 512 + jb + hcl]           = h;  // h_T
                out[(size_t)BT_ * H_ + B_ * H_ + bb * 512 + jb + hcl] = c;  // c_T
            }
        }
        __syncthreads();   // all g_h stores done before the arrive below

        if (t < T_ - 1) {
            const unsigned step = (unsigned)t + 1u;
            if (tid == 0) st_rel_u32(&g_flags[j], fbase + step);  // arrive
            if (j == 0) {
                // Master: aggregate 128 flags (coalesced), then release.
                if (tid < NCTA_REC) {
                    while ((int)(ld_acq_u32(&g_flags[tid]) - (fbase + step)) < 0) { }
                }
                __syncthreads();
                if (tid == 0) st_rel_u32(&g_go, gbase + step);
            } else {
                // Others: one thread polls the single release word.
                if (tid == 0) {
                    while ((int)(ld_acq_u32(&g_go) - (gbase + step)) < 0) { }
                }
                __syncthreads();
            }
        }
    }
}

// ---------------------------------------------------------------------------
// Launcher
// ---------------------------------------------------------------------------
extern "C" void kernel_launch(void* const* d_in, const int* in_sizes, int n_in,
                              void* d_out, int out_size) {
    const float* x    = (const float*)d_in[0];   // (B, T, D)
    const float* W    = (const float*)d_in[1];   // (D+H, 4H)
    const float* bias = (const float*)d_in[2];   // (4H,)
    const float* h0   = (const float*)d_in[3];   // (B, H)
    const float* c0   = (const float*)d_in[4];   // (B, H)
    float* out = (float*)d_out;                  // outputs | h_T | c_T

    dim3 grid(G_ / 128, BT_ / 128);
    xg_gemm<<<grid, 256>>>(x, W, bias);

    size_t smem = SMEM_FLOATS * sizeof(float);
    cudaFuncSetAttribute(lstm_rec, cudaFuncAttributeMaxDynamicSharedMemorySize,
                         (int)smem);
    lstm_rec<<<NCTA_REC, 256, smem>>>(W, h0, c0, out);
}